// round 1
// baseline (speedup 1.0000x reference)
#include <cuda_runtime.h>

#define N_AGENTS 16384
#define OBS_DIM  2048
#define HID      512
#define N_ACT    32

// 32 MB scratch for the hidden activations (allocation-free rule: __device__ global).
__device__ float g_hidden[(size_t)N_AGENTS * HID];

// ---------------------------------------------------------------------------
// packed fp32x2 helpers (Blackwell dual-rate fp32; only reachable via PTX)
// ---------------------------------------------------------------------------
__device__ __forceinline__ void ffma2(unsigned long long& d, unsigned long long a, unsigned long long b) {
    asm("fma.rn.f32x2 %0, %1, %2, %0;" : "+l"(d) : "l"(a), "l"(b));
}
__device__ __forceinline__ unsigned long long pack2(float lo, float hi) {
    unsigned long long r;
    asm("mov.b64 %0, {%1, %2};" : "=l"(r) : "f"(lo), "f"(hi));
    return r;
}

// ---------------------------------------------------------------------------
// Kernel 1: hidden = relu(x @ W_enc^T + b_enc)
//   A = x     [16384, 2048]  (row-major, K contiguous)
//   B = W_enc [  512, 2048]  (row-major, K contiguous)
//   C = g_hidden [16384, 512]
// Tiles: BM=128, BN=128, BK=16; 256 threads, 8x8 microtile per thread,
// accumulators packed as f32x2 pairs along M.
// ---------------------------------------------------------------------------
#define BM 128
#define BN 128
#define BK 16

__global__ __launch_bounds__(256, 2) void enc_gemm(
    const float* __restrict__ A, const float* __restrict__ B, const float* __restrict__ bias)
{
    __shared__ __align__(16) float As[BK][BM];
    __shared__ __align__(16) float Bs[BK][BN];

    const int tid = threadIdx.x;
    const int m0 = blockIdx.y * BM;
    const int n0 = blockIdx.x * BN;
    const int tx = tid & 15;   // n-direction (8 cols)
    const int ty = tid >> 4;   // m-direction (8 rows)

    unsigned long long acc[4][8];   // [m-pair][n] : 64 fp32 accumulators
#pragma unroll
    for (int i = 0; i < 4; i++)
#pragma unroll
        for (int j = 0; j < 8; j++) acc[i][j] = 0ull;

    const int r0  = tid >> 2;          // 0..63
    const int kq0 = (tid & 3) << 2;    // 0,4,8,12

    for (int kt = 0; kt < OBS_DIM; kt += BK) {
#pragma unroll
        for (int l = 0; l < 2; l++) {
            const int r = r0 + l * 64;
            float4 va = *(const float4*)(A + (size_t)(m0 + r) * OBS_DIM + kt + kq0);
            As[kq0 + 0][r] = va.x; As[kq0 + 1][r] = va.y;
            As[kq0 + 2][r] = va.z; As[kq0 + 3][r] = va.w;
            float4 vb = *(const float4*)(B + (size_t)(n0 + r) * OBS_DIM + kt + kq0);
            Bs[kq0 + 0][r] = vb.x; Bs[kq0 + 1][r] = vb.y;
            Bs[kq0 + 2][r] = vb.z; Bs[kq0 + 3][r] = vb.w;
        }
        __syncthreads();

#pragma unroll
        for (int k = 0; k < BK; k++) {
            // A fragment: 8 consecutive M values = 4 f32x2 pairs (warp-broadcast LDS)
            const ulonglong2* ap2 = (const ulonglong2*)&As[k][ty * 8];
            ulonglong2 a01 = ap2[0];
            ulonglong2 a23 = ap2[1];
            unsigned long long ap[4] = { a01.x, a01.y, a23.x, a23.y };
            // B fragment: 8 N values, each duplicated into both f32x2 lanes
            float4 b0 = *(const float4*)&Bs[k][tx * 8];
            float4 b1 = *(const float4*)&Bs[k][tx * 8 + 4];
            unsigned long long bp[8] = {
                pack2(b0.x, b0.x), pack2(b0.y, b0.y), pack2(b0.z, b0.z), pack2(b0.w, b0.w),
                pack2(b1.x, b1.x), pack2(b1.y, b1.y), pack2(b1.z, b1.z), pack2(b1.w, b1.w)
            };
#pragma unroll
            for (int i = 0; i < 4; i++)
#pragma unroll
                for (int j = 0; j < 8; j++)
                    ffma2(acc[i][j], ap[i], bp[j]);
        }
        __syncthreads();
    }

    // epilogue: +bias, ReLU, store
    float bv[8];
#pragma unroll
    for (int j = 0; j < 8; j++) bv[j] = bias[n0 + tx * 8 + j];
#pragma unroll
    for (int i = 0; i < 4; i++) {
        float lo[8], hi[8];
#pragma unroll
        for (int j = 0; j < 8; j++) {
            float vx, vy;
            asm("mov.b64 {%0, %1}, %2;" : "=f"(vx), "=f"(vy) : "l"(acc[i][j]));
            lo[j] = fmaxf(vx + bv[j], 0.f);
            hi[j] = fmaxf(vy + bv[j], 0.f);
        }
        const size_t m = (size_t)(m0 + ty * 8 + 2 * i);
        float* o = g_hidden + m * HID + n0 + tx * 8;
        *(float4*)(o)           = make_float4(lo[0], lo[1], lo[2], lo[3]);
        *(float4*)(o + 4)       = make_float4(lo[4], lo[5], lo[6], lo[7]);
        *(float4*)(o + HID)     = make_float4(hi[0], hi[1], hi[2], hi[3]);
        *(float4*)(o + HID + 4) = make_float4(hi[4], hi[5], hi[6], hi[7]);
    }
}

// ---------------------------------------------------------------------------
// Kernel 2: per-agent heads. One warp handles 2 agents.
//   logits[a] = hidden . Ws[a] + bs[a]   (a = 0..31, lane-parallel after transpose)
//   value     = hidden . Wc + bc
//   log-softmax, logprob gather, entropy; manager_logprob = -ln(16) const.
// Output layout: [action | sampled_skill | mlogp | slogp | entropy | value],
// each 16384 fp32.
// ---------------------------------------------------------------------------
__global__ __launch_bounds__(256) void head_kernel(
    const float* __restrict__ Ws, const float* __restrict__ bs,
    const float* __restrict__ Wc, const float* __restrict__ bc,
    const int* __restrict__ skill, const int* __restrict__ action,
    float* __restrict__ out)
{
    __shared__ float red[8][32][33];   // [warp][src lane][logit idx], padded col
    const int lane = threadIdx.x & 31;
    const int w    = threadIdx.x >> 5;
    const int a0   = (blockIdx.x * 8 + w) * 2;   // grid sized exactly: no bounds check

    const float* h0 = g_hidden + (size_t)a0 * HID;

    float acc[2][33];
#pragma unroll
    for (int s = 0; s < 2; s++)
#pragma unroll
        for (int i = 0; i < 33; i++) acc[s][i] = 0.f;

#pragma unroll 4
    for (int j = 0; j < HID / 32; j++) {
        const int k = j * 32 + lane;
        const float hv0 = h0[k];
        const float hv1 = h0[HID + k];
#pragma unroll
        for (int t = 0; t < 32; t++) {
            const float wv = Ws[t * HID + k];
            acc[0][t] += hv0 * wv;
            acc[1][t] += hv1 * wv;
        }
        const float wc = Wc[k];
        acc[0][32] += hv0 * wc;
        acc[1][32] += hv1 * wc;
    }

    const float bsl = bs[lane];
    const float bcv = bc[0];

#pragma unroll
    for (int s = 0; s < 2; s++) {
        const int agent = a0 + s;

        // value: butterfly reduce
        float v = acc[s][32];
#pragma unroll
        for (int o = 16; o > 0; o >>= 1) v += __shfl_xor_sync(0xffffffffu, v, o);

        // logits: transpose-reduce through padded smem (lane ends owning logit[lane])
#pragma unroll
        for (int t = 0; t < 32; t++) red[w][lane][t] = acc[s][t];
        __syncwarp();
        float logit = 0.f;
#pragma unroll
        for (int l = 0; l < 32; l++) logit += red[w][l][lane];
        __syncwarp();
        logit += bsl;

        // in-warp log-softmax
        float mx = logit;
#pragma unroll
        for (int o = 16; o > 0; o >>= 1) mx = fmaxf(mx, __shfl_xor_sync(0xffffffffu, mx, o));
        const float e = expf(logit - mx);
        float se = e;
#pragma unroll
        for (int o = 16; o > 0; o >>= 1) se += __shfl_xor_sync(0xffffffffu, se, o);
        const float lse = mx + logf(se);
        const float lsm = logit - lse;
        float ent = -(e / se) * lsm;
#pragma unroll
        for (int o = 16; o > 0; o >>= 1) ent += __shfl_xor_sync(0xffffffffu, ent, o);

        const int act = action[agent];
        const float slp = __shfl_sync(0xffffffffu, lsm, act & 31);

        if (lane == 0) {
            out[0 * N_AGENTS + agent] = (float)act;
            out[1 * N_AGENTS + agent] = (float)skill[agent];
            out[2 * N_AGENTS + agent] = -2.7725887222397811f;  // -ln(16)
            out[3 * N_AGENTS + agent] = slp;
            out[4 * N_AGENTS + agent] = ent;
            out[5 * N_AGENTS + agent] = v + bcv;
        }
    }
}

// ---------------------------------------------------------------------------
// launch
// ---------------------------------------------------------------------------
extern "C" void kernel_launch(void* const* d_in, const int* in_sizes, int n_in,
                              void* d_out, int out_size) {
    (void)in_sizes; (void)n_in; (void)out_size;
    const float* x     = (const float*)d_in[0];
    const float* W_enc = (const float*)d_in[1];
    const float* b_enc = (const float*)d_in[2];
    // d_in[3] = Wm, d_in[4] = bm : dead code (selections never returned)
    const float* Ws    = (const float*)d_in[5];
    const float* bs    = (const float*)d_in[6];
    const float* Wc    = (const float*)d_in[7];
    const float* bc    = (const float*)d_in[8];
    const int*   skill = (const int*)d_in[9];
    const int*   act   = (const int*)d_in[10];
    float* out = (float*)d_out;

    dim3 g1(HID / BN, N_AGENTS / BM);   // (4, 128)
    enc_gemm<<<g1, 256>>>(x, W_enc, b_enc);

    head_kernel<<<N_AGENTS / 16, 256>>>(Ws, bs, Wc, bc, skill, act, out);
}

// round 3
// speedup vs baseline: 1.6170x; 1.6170x over previous
#include <cuda_runtime.h>
#include <cuda_bf16.h>
#include <stdint.h>

#define N_AGENTS 16384
#define OBS_DIM  2048
#define HID      512

// ---- mma.sync GEMM tiling ----
#define BM 128
#define BN 128
#define KC 64                    // bf16 K per chunk (128B rows)
#define NCHUNK (OBS_DIM / KC)    // 32
#define NTILES (HID / BN)        // 4

#define SA_HI 0
#define SA_LO 16384
#define SB_HI 32768
#define SB_LO 49152
#define STAGE 65536
#define SMEM_TOTAL (2 * STAGE + 512)

__device__ float g_hidden[(size_t)N_AGENTS * HID];
// pre-converted, pre-swizzled W_enc: [ntile][chunk][hi/lo][128 rows x 128B]
__device__ __align__(1024) unsigned char g_Bstage[(size_t)NTILES * NCHUNK * 2 * 16384];

static __device__ __forceinline__ uint32_t smem_addr_u32(const void* p) {
    uint32_t a;
    asm("{ .reg .u64 t; cvta.to.shared.u64 t, %1; cvt.u32.u64 %0, t; }" : "=r"(a) : "l"(p));
    return a;
}

static __device__ __forceinline__ void ldm_x4(uint32_t* r, uint32_t addr) {
    asm volatile("ldmatrix.sync.aligned.m8n8.x4.shared.b16 {%0,%1,%2,%3}, [%4];"
                 : "=r"(r[0]), "=r"(r[1]), "=r"(r[2]), "=r"(r[3]) : "r"(addr));
}

static __device__ __forceinline__ void mma_bf16(float* c, const uint32_t* a,
                                                const uint32_t* b) {
    asm volatile(
        "mma.sync.aligned.m16n8k16.row.col.f32.bf16.bf16.f32 "
        "{%0,%1,%2,%3}, {%4,%5,%6,%7}, {%8,%9}, {%0,%1,%2,%3};"
        : "+f"(c[0]), "+f"(c[1]), "+f"(c[2]), "+f"(c[3])
        : "r"(a[0]), "r"(a[1]), "r"(a[2]), "r"(a[3]), "r"(b[0]), "r"(b[1]));
}

static __device__ __forceinline__ void split2(float x0, float x1, uint32_t& hi, uint32_t& lo) {
    __nv_bfloat16 h0 = __float2bfloat16(x0);
    __nv_bfloat16 h1 = __float2bfloat16(x1);
    __nv_bfloat16 l0 = __float2bfloat16(x0 - __bfloat162float(h0));
    __nv_bfloat16 l1 = __float2bfloat16(x1 - __bfloat162float(h1));
    __nv_bfloat162 hp; hp.x = h0; hp.y = h1;
    __nv_bfloat162 lp; lp.x = l0; lp.y = l1;
    hi = *(uint32_t*)&hp;
    lo = *(uint32_t*)&lp;
}

// ---------------------------------------------------------------------------
// Pre-kernel: W_enc fp32 -> (hi,lo) bf16, pre-swizzled tile layout
// ---------------------------------------------------------------------------
__global__ void conv_w_kernel(const float* __restrict__ W) {
    int gid = blockIdx.x * 256 + threadIdx.x;   // 131072 threads
    int n   = gid >> 8;                          // 0..511
    int k0  = (gid & 255) << 3;                  // 0..2040 step 8
    const float* src = W + (size_t)n * OBS_DIM + k0;
    float4 v0 = *(const float4*)src;
    float4 v1 = *(const float4*)(src + 4);
    float f[8] = {v0.x, v0.y, v0.z, v0.w, v1.x, v1.y, v1.z, v1.w};

    uint32_t hi[4], lo[4];
#pragma unroll
    for (int j = 0; j < 4; j++) split2(f[2 * j], f[2 * j + 1], hi[j], lo[j]);

    int c  = k0 >> 6;          // chunk
    int kl = k0 & 63;          // k within chunk (floats)
    int t  = n >> 7;           // ntile (BN=128)
    int nl = n & 127;
    uint32_t byte = (uint32_t)nl * 128 + (((uint32_t)kl * 2) ^ ((uint32_t)(nl & 7) << 4));
    unsigned char* blk = g_Bstage + ((size_t)(t * NCHUNK + c) * 2) * 16384;
    *(uint4*)(blk + byte)         = make_uint4(hi[0], hi[1], hi[2], hi[3]);
    *(uint4*)(blk + 16384 + byte) = make_uint4(lo[0], lo[1], lo[2], lo[3]);
}

// ---------------------------------------------------------------------------
// HMMA GEMM: g_hidden = relu(x @ W_enc^T + b_enc), bf16 hi/lo 3-term split
// ---------------------------------------------------------------------------
__global__ __launch_bounds__(256, 1) void enc_gemm_mma(
    const float* __restrict__ A, const float* __restrict__ bias)
{
    extern __shared__ __align__(1024) unsigned char smem[];
    const int tid = threadIdx.x;
    const int w = tid >> 5, l = tid & 31;
    const int mtile = blockIdx.x >> 2;
    const int ntile = blockIdx.x & 3;
    const int m0 = mtile * BM;
    const int n0 = ntile * BN;
    const uint32_t sb = smem_addr_u32(smem);
    float* bsm = (float*)(smem + 2 * STAGE);
    if (tid < 128) bsm[tid] = bias[n0 + tid];

    // A loader mapping: thread covers row r, half h (32 floats)
    const int r = tid >> 1, h = tid & 1;
    const float* aptr = A + (size_t)(m0 + r) * OBS_DIM + h * 32;
    const unsigned char* gB = g_Bstage + (size_t)ntile * NCHUNK * 32768;

    float acc[4][4][4];
#pragma unroll
    for (int i = 0; i < 4; i++)
#pragma unroll
        for (int j = 0; j < 4; j++)
#pragma unroll
            for (int q = 0; q < 4; q++) acc[i][j][q] = 0.f;

    const int wm = (w >> 2) * 64;
    const int wn = (w & 3) * 32;
    const int idx = l & 7, seg = l >> 3;
    const int arl = idx + (seg & 1) * 8;       // A row within m16 tile
    const int acb = (seg >> 1) * 16;           // A k-byte sub-offset
    const int brl = idx + (seg >> 1) * 8;      // B row within n16 group
    const int bkb = (seg & 1) * 16;            // B k-byte sub-offset
    const uint32_t sxor = (uint32_t)idx << 4;  // SW128 reduces to this XOR

    float av[32];

#define LOADA(c)                                                               \
    {                                                                          \
        const float4* s4 = (const float4*)(aptr + (c) * KC);                   \
        _Pragma("unroll") for (int i = 0; i < 8; i++) *(float4*)(av + 4 * i) = s4[i]; \
    }

#define STSA(stg)                                                              \
    {                                                                          \
        unsigned char* st = smem + (stg) * STAGE;                              \
        _Pragma("unroll") for (int q = 0; q < 4; q++) {                        \
            uint32_t hi_[4], lo_[4];                                           \
            _Pragma("unroll") for (int j = 0; j < 4; j++)                      \
                split2(av[q * 8 + 2 * j], av[q * 8 + 2 * j + 1], hi_[j], lo_[j]); \
            uint32_t byte = (uint32_t)r * 128 +                                \
                (((uint32_t)(h * 64 + q * 16)) ^ ((uint32_t)(r & 7) << 4));    \
            *(uint4*)(st + SA_HI + byte) = make_uint4(hi_[0], hi_[1], hi_[2], hi_[3]); \
            *(uint4*)(st + SA_LO + byte) = make_uint4(lo_[0], lo_[1], lo_[2], lo_[3]); \
        }                                                                      \
    }

#define CPB(c, stg)                                                            \
    {                                                                          \
        uint32_t dst = sb + (stg) * STAGE + SB_HI;                             \
        const unsigned char* g = gB + (size_t)(c) * 32768;                     \
        _Pragma("unroll") for (int i = 0; i < 8; i++) {                        \
            uint32_t off = (uint32_t)(i * 256 + tid) * 16;                     \
            asm volatile("cp.async.cg.shared.global [%0], [%1], 16;"           \
                         :: "r"(dst + off), "l"(g + off) : "memory");          \
        }                                                                      \
        asm volatile("cp.async.commit_group;" ::: "memory");                   \
    }

    // prologue: fill stage 0
    LOADA(0);
    CPB(0, 0);
    STSA(0);
    asm volatile("cp.async.wait_group 0;" ::: "memory");
    __syncthreads();

    for (int c = 0; c < NCHUNK; c++) {
        const int s = c & 1;
        if (c + 1 < NCHUNK) {
            LOADA(c + 1);
            CPB(c + 1, s ^ 1);
        }

        const uint32_t stA_hi = sb + s * STAGE + SA_HI;
        const uint32_t stA_lo = sb + s * STAGE + SA_LO;
        const uint32_t stB_hi = sb + s * STAGE + SB_HI;
        const uint32_t stB_lo = sb + s * STAGE + SB_LO;

#pragma unroll
        for (int ks = 0; ks < 4; ks++) {
            const int kb = ks * 32;
            uint32_t ah[4][4], al[4][4], bh[8], bl[8];
#pragma unroll
            for (int mt = 0; mt < 4; mt++) {
                uint32_t off = (uint32_t)(wm + mt * 16 + arl) * 128 +
                               (((uint32_t)(kb + acb)) ^ sxor);
                ldm_x4(ah[mt], stA_hi + off);
                ldm_x4(al[mt], stA_lo + off);
            }
#pragma unroll
            for (int g = 0; g < 2; g++) {
                uint32_t off = (uint32_t)(wn + g * 16 + brl) * 128 +
                               (((uint32_t)(kb + bkb)) ^ sxor);
                ldm_x4(&bh[g * 4], stB_hi + off);
                ldm_x4(&bl[g * 4], stB_lo + off);
            }
#pragma unroll
            for (int mt = 0; mt < 4; mt++)
#pragma unroll
                for (int nt = 0; nt < 4; nt++) {
                    mma_bf16(acc[mt][nt], ah[mt], &bh[nt * 2]);
                    mma_bf16(acc[mt][nt], ah[mt], &bl[nt * 2]);
                    mma_bf16(acc[mt][nt], al[mt], &bh[nt * 2]);
                }
        }

        if (c + 1 < NCHUNK) {
            STSA(s ^ 1);
            asm volatile("cp.async.wait_group 0;" ::: "memory");
        }
        __syncthreads();
    }

    // epilogue: bias + relu + store
#pragma unroll
    for (int mt = 0; mt < 4; mt++)
#pragma unroll
        for (int nt = 0; nt < 4; nt++) {
            const int colL = wn + nt * 8 + (l & 3) * 2;
            const float b0 = bsm[colL], b1 = bsm[colL + 1];
            const int row = m0 + wm + mt * 16 + (l >> 2);
            float2 o0, o1;
            o0.x = fmaxf(acc[mt][nt][0] + b0, 0.f);
            o0.y = fmaxf(acc[mt][nt][1] + b1, 0.f);
            o1.x = fmaxf(acc[mt][nt][2] + b0, 0.f);
            o1.y = fmaxf(acc[mt][nt][3] + b1, 0.f);
            *(float2*)(g_hidden + (size_t)row * HID + n0 + colL) = o0;
            *(float2*)(g_hidden + (size_t)(row + 8) * HID + n0 + colL) = o1;
        }
}

// ---------------------------------------------------------------------------
// Heads: one warp per 2 agents; Ws/Wc staged in smem (fixes L2-bound re-reads)
// ---------------------------------------------------------------------------
#define RED_OFF 0
#define WS_OFF  33792                   // 8*32*33*4
#define WC_OFF  (WS_OFF + 32 * 512 * 4)
#define HEAD_SMEM (WC_OFF + 512 * 4)    // 101376 B

__global__ __launch_bounds__(256) void head_kernel(
    const float* __restrict__ Ws, const float* __restrict__ bs,
    const float* __restrict__ Wc, const float* __restrict__ bc,
    const int* __restrict__ skill, const int* __restrict__ action,
    float* __restrict__ out)
{
    extern __shared__ __align__(16) unsigned char hsm[];
    float* red  = (float*)(hsm + RED_OFF);   // [8][32][33]
    float* ws_s = (float*)(hsm + WS_OFF);    // [32][512]
    float* wc_s = (float*)(hsm + WC_OFF);    // [512]

    const int tid = threadIdx.x;
#pragma unroll
    for (int i = 0; i < 16; i++)
        ((float4*)ws_s)[i * 256 + tid] = ((const float4*)Ws)[i * 256 + tid];
    if (tid < 128) ((float4*)wc_s)[tid] = ((const float4*)Wc)[tid];
    __syncthreads();

    const int lane = tid & 31;
    const int w    = tid >> 5;
    const int a0   = (blockIdx.x * 8 + w) * 2;

    const float* h0 = g_hidden + (size_t)a0 * HID;

    float acc[2][33];
#pragma unroll
    for (int s = 0; s < 2; s++)
#pragma unroll
        for (int i = 0; i < 33; i++) acc[s][i] = 0.f;

#pragma unroll 4
    for (int j = 0; j < HID / 32; j++) {
        const int k = j * 32 + lane;
        const float hv0 = h0[k];
        const float hv1 = h0[HID + k];
#pragma unroll
        for (int t = 0; t < 32; t++) {
            const float wv = ws_s[t * HID + k];
            acc[0][t] += hv0 * wv;
            acc[1][t] += hv1 * wv;
        }
        const float wc = wc_s[k];
        acc[0][32] += hv0 * wc;
        acc[1][32] += hv1 * wc;
    }

    const float bsl = bs[lane];
    const float bcv = bc[0];
    float* redw = red + w * 32 * 33;

#pragma unroll
    for (int s = 0; s < 2; s++) {
        const int agent = a0 + s;

        float v = acc[s][32];
#pragma unroll
        for (int o = 16; o > 0; o >>= 1) v += __shfl_xor_sync(0xffffffffu, v, o);

#pragma unroll
        for (int t = 0; t < 32; t++) redw[lane * 33 + t] = acc[s][t];
        __syncwarp();
        float logit = 0.f;
#pragma unroll
        for (int q = 0; q < 32; q++) logit += redw[q * 33 + lane];
        __syncwarp();
        logit += bsl;

        float mx = logit;
#pragma unroll
        for (int o = 16; o > 0; o >>= 1) mx = fmaxf(mx, __shfl_xor_sync(0xffffffffu, mx, o));
        const float e = expf(logit - mx);
        float se = e;
#pragma unroll
        for (int o = 16; o > 0; o >>= 1) se += __shfl_xor_sync(0xffffffffu, se, o);
        const float lse = mx + logf(se);
        const float lsm = logit - lse;
        float ent = -(e / se) * lsm;
#pragma unroll
        for (int o = 16; o > 0; o >>= 1) ent += __shfl_xor_sync(0xffffffffu, ent, o);

        const int act = action[agent];
        const float slp = __shfl_sync(0xffffffffu, lsm, act & 31);

        if (lane == 0) {
            out[0 * N_AGENTS + agent] = (float)act;
            out[1 * N_AGENTS + agent] = (float)skill[agent];
            out[2 * N_AGENTS + agent] = -2.7725887222397811f;  // -ln(16)
            out[3 * N_AGENTS + agent] = slp;
            out[4 * N_AGENTS + agent] = ent;
            out[5 * N_AGENTS + agent] = v + bcv;
        }
    }
}

// ---------------------------------------------------------------------------
// launch
// ---------------------------------------------------------------------------
extern "C" void kernel_launch(void* const* d_in, const int* in_sizes, int n_in,
                              void* d_out, int out_size) {
    (void)in_sizes; (void)n_in; (void)out_size;
    const float* x     = (const float*)d_in[0];
    const float* W_enc = (const float*)d_in[1];
    const float* b_enc = (const float*)d_in[2];
    // d_in[3]=Wm, d_in[4]=bm : dead (selections never returned)
    const float* Ws    = (const float*)d_in[5];
    const float* bs    = (const float*)d_in[6];
    const float* Wc    = (const float*)d_in[7];
    const float* bc    = (const float*)d_in[8];
    const int*   skill = (const int*)d_in[9];
    const int*   act   = (const int*)d_in[10];
    float* out = (float*)d_out;

    conv_w_kernel<<<512, 256>>>(W_enc);

    static int cfg_done = 0;
    if (!cfg_done) {
        cudaFuncSetAttribute(enc_gemm_mma, cudaFuncAttributeMaxDynamicSharedMemorySize,
                             SMEM_TOTAL);
        cudaFuncSetAttribute(head_kernel, cudaFuncAttributeMaxDynamicSharedMemorySize,
                             HEAD_SMEM);
        cfg_done = 1;
    }

    enc_gemm_mma<<<NTILES * (N_AGENTS / BM), 256, SMEM_TOTAL>>>(x, b_enc);

    head_kernel<<<N_AGENTS / 16, 256, HEAD_SMEM>>>(Ws, bs, Wc, bc, skill, act, out);
}

// round 4
// speedup vs baseline: 3.0392x; 1.8796x over previous
#include <cuda_runtime.h>
#include <cuda_bf16.h>
#include <stdint.h>

#define N_AGENTS 16384
#define OBS_DIM  2048
#define HID      512

// ---- mma.sync GEMM tiling ----
#define BM 128
#define BN 128
#define KC 64                    // bf16 K per chunk (128B rows)
#define NCHUNK (OBS_DIM / KC)    // 32
#define NTILES (HID / BN)        // 4
#define MTILES (N_AGENTS / BM)   // 128

#define SA_HI 0
#define SA_LO 16384
#define SB_HI 32768
#define SB_LO 49152
#define STAGE 65536              // A(hi+lo 32K) + B(hi+lo 32K)
#define NSTAGE 3
#define SMEM_TOTAL (NSTAGE * STAGE + 512)   // 197120

__device__ float g_hidden[(size_t)N_AGENTS * HID];
// pre-converted, pre-swizzled tiles: [tile][chunk][hi 16K | lo 16K]
__device__ __align__(1024) unsigned char g_Bstage[(size_t)NTILES * NCHUNK * 32768];
__device__ __align__(1024) unsigned char g_Astage[(size_t)MTILES * NCHUNK * 32768];

static __device__ __forceinline__ uint32_t smem_addr_u32(const void* p) {
    uint32_t a;
    asm("{ .reg .u64 t; cvta.to.shared.u64 t, %1; cvt.u32.u64 %0, t; }" : "=r"(a) : "l"(p));
    return a;
}

static __device__ __forceinline__ void ldm_x4(uint32_t* r, uint32_t addr) {
    asm volatile("ldmatrix.sync.aligned.m8n8.x4.shared.b16 {%0,%1,%2,%3}, [%4];"
                 : "=r"(r[0]), "=r"(r[1]), "=r"(r[2]), "=r"(r[3]) : "r"(addr));
}

static __device__ __forceinline__ void mma_bf16(float* c, const uint32_t* a,
                                                const uint32_t* b) {
    asm volatile(
        "mma.sync.aligned.m16n8k16.row.col.f32.bf16.bf16.f32 "
        "{%0,%1,%2,%3}, {%4,%5,%6,%7}, {%8,%9}, {%0,%1,%2,%3};"
        : "+f"(c[0]), "+f"(c[1]), "+f"(c[2]), "+f"(c[3])
        : "r"(a[0]), "r"(a[1]), "r"(a[2]), "r"(a[3]), "r"(b[0]), "r"(b[1]));
}

static __device__ __forceinline__ void split2(float x0, float x1, uint32_t& hi, uint32_t& lo) {
    __nv_bfloat16 h0 = __float2bfloat16(x0);
    __nv_bfloat16 h1 = __float2bfloat16(x1);
    __nv_bfloat16 l0 = __float2bfloat16(x0 - __bfloat162float(h0));
    __nv_bfloat16 l1 = __float2bfloat16(x1 - __bfloat162float(h1));
    __nv_bfloat162 hp; hp.x = h0; hp.y = h1;
    __nv_bfloat162 lp; lp.x = l0; lp.y = l1;
    hi = *(uint32_t*)&hp;
    lo = *(uint32_t*)&lp;
}

// ---------------------------------------------------------------------------
// Pre-convert: fp32 [rows x 2048] -> pre-swizzled hi/lo bf16 tile staging.
// Tile = 128 rows x 64 k (hi 16KB | lo 16KB). Used for both x and W_enc.
// ---------------------------------------------------------------------------
__global__ void conv_kernel(const float* __restrict__ S, unsigned char* __restrict__ D) {
    const int gid = blockIdx.x * 256 + threadIdx.x;
    const int n   = gid >> 8;                  // row
    const int k0  = (gid & 255) << 3;          // 8-float column offset
    const float* src = S + (size_t)n * OBS_DIM + k0;
    float4 v0 = *(const float4*)src;
    float4 v1 = *(const float4*)(src + 4);
    float f[8] = {v0.x, v0.y, v0.z, v0.w, v1.x, v1.y, v1.z, v1.w};

    uint32_t hi[4], lo[4];
#pragma unroll
    for (int j = 0; j < 4; j++) split2(f[2 * j], f[2 * j + 1], hi[j], lo[j]);

    const int c  = k0 >> 6;                    // chunk
    const int kl = k0 & 63;                    // k within chunk
    const int t  = n >> 7;                     // tile
    const int nl = n & 127;                    // row within tile
    const uint32_t byte = (uint32_t)nl * 128 +
                          (((uint32_t)kl * 2) ^ ((uint32_t)(nl & 7) << 4));
    unsigned char* blk = D + ((size_t)(t * NCHUNK + c)) * 32768;
    *(uint4*)(blk + byte)         = make_uint4(hi[0], hi[1], hi[2], hi[3]);
    *(uint4*)(blk + 16384 + byte) = make_uint4(lo[0], lo[1], lo[2], lo[3]);
}

// ---------------------------------------------------------------------------
// HMMA GEMM, pure streaming: g_hidden = relu(x @ W_enc^T + b_enc)
// 3-term bf16 hi/lo split; 3-stage cp.async ring; zero conversion in-loop.
// ---------------------------------------------------------------------------
__global__ __launch_bounds__(256, 1) void enc_gemm_mma(const float* __restrict__ bias) {
    extern __shared__ __align__(1024) unsigned char smem[];
    const int tid = threadIdx.x;
    const int w = tid >> 5, l = tid & 31;
    const int mtile = blockIdx.x >> 2;
    const int ntile = blockIdx.x & 3;
    const int m0 = mtile * BM;
    const int n0 = ntile * BN;
    const uint32_t sb = smem_addr_u32(smem);
    float* bsm = (float*)(smem + NSTAGE * STAGE);
    if (tid < 128) bsm[tid] = bias[n0 + tid];

    const unsigned char* gA = g_Astage + (size_t)mtile * NCHUNK * 32768;
    const unsigned char* gB = g_Bstage + (size_t)ntile * NCHUNK * 32768;

    float acc[4][4][4];
#pragma unroll
    for (int i = 0; i < 4; i++)
#pragma unroll
        for (int j = 0; j < 4; j++)
#pragma unroll
            for (int q = 0; q < 4; q++) acc[i][j][q] = 0.f;

    const int wm = (w >> 2) * 64;
    const int wn = (w & 3) * 32;
    const int idx = l & 7, seg = l >> 3;
    const int arl = idx + (seg & 1) * 8;       // A row within m16 tile
    const int acb = (seg >> 1) * 16;           // A k-byte sub-offset
    const int brl = idx + (seg >> 1) * 8;      // B row within n16 group
    const int bkb = (seg & 1) * 16;            // B k-byte sub-offset
    const uint32_t sxor = (uint32_t)idx << 4;  // SW128 reduces to this XOR

#define ISSUE(c, slot)                                                         \
    {                                                                          \
        const uint32_t dst = sb + (slot) * STAGE;                              \
        const unsigned char* ga = gA + (size_t)(c) * 32768;                    \
        const unsigned char* gb = gB + (size_t)(c) * 32768;                    \
        _Pragma("unroll") for (int i = 0; i < 8; i++) {                        \
            uint32_t off = (uint32_t)(i * 256 + tid) * 16;                     \
            asm volatile("cp.async.cg.shared.global [%0], [%1], 16;"           \
                         :: "r"(dst + off), "l"(ga + off) : "memory");         \
        }                                                                      \
        _Pragma("unroll") for (int i = 0; i < 8; i++) {                        \
            uint32_t off = (uint32_t)(i * 256 + tid) * 16;                     \
            asm volatile("cp.async.cg.shared.global [%0], [%1], 16;"           \
                         :: "r"(dst + SB_HI + off), "l"(gb + off) : "memory"); \
        }                                                                      \
        asm volatile("cp.async.commit_group;" ::: "memory");                   \
    }

    ISSUE(0, 0);
    ISSUE(1, 1);

    int slot = 0;
    for (int c = 0; c < NCHUNK; c++) {
        if (c + 2 < NCHUNK) {
            asm volatile("cp.async.wait_group 1;" ::: "memory");
        } else {
            asm volatile("cp.async.wait_group 0;" ::: "memory");
        }
        __syncthreads();

        if (c + 2 < NCHUNK) {
            const int ns = (slot + 2 >= NSTAGE) ? slot + 2 - NSTAGE : slot + 2;
            ISSUE(c + 2, ns);
        }

        const uint32_t stA_hi = sb + slot * STAGE + SA_HI;
        const uint32_t stA_lo = sb + slot * STAGE + SA_LO;
        const uint32_t stB_hi = sb + slot * STAGE + SB_HI;
        const uint32_t stB_lo = sb + slot * STAGE + SB_LO;

#pragma unroll
        for (int ks = 0; ks < 4; ks++) {
            const int kb = ks * 32;
            uint32_t ah[4][4], al[4][4], bh[8], bl[8];
#pragma unroll
            for (int mt = 0; mt < 4; mt++) {
                uint32_t off = (uint32_t)(wm + mt * 16 + arl) * 128 +
                               (((uint32_t)(kb + acb)) ^ sxor);
                ldm_x4(ah[mt], stA_hi + off);
                ldm_x4(al[mt], stA_lo + off);
            }
#pragma unroll
            for (int g = 0; g < 2; g++) {
                uint32_t off = (uint32_t)(wn + g * 16 + brl) * 128 +
                               (((uint32_t)(kb + bkb)) ^ sxor);
                ldm_x4(&bh[g * 4], stB_hi + off);
                ldm_x4(&bl[g * 4], stB_lo + off);
            }
#pragma unroll
            for (int mt = 0; mt < 4; mt++)
#pragma unroll
                for (int nt = 0; nt < 4; nt++) {
                    mma_bf16(acc[mt][nt], ah[mt], &bh[nt * 2]);
                    mma_bf16(acc[mt][nt], ah[mt], &bl[nt * 2]);
                    mma_bf16(acc[mt][nt], al[mt], &bh[nt * 2]);
                }
        }

        slot = (slot + 1 >= NSTAGE) ? 0 : slot + 1;
    }

    // epilogue: bias + relu + store
#pragma unroll
    for (int mt = 0; mt < 4; mt++)
#pragma unroll
        for (int nt = 0; nt < 4; nt++) {
            const int colL = wn + nt * 8 + (l & 3) * 2;
            const float b0 = bsm[colL], b1 = bsm[colL + 1];
            const int row = m0 + wm + mt * 16 + (l >> 2);
            float2 o0, o1;
            o0.x = fmaxf(acc[mt][nt][0] + b0, 0.f);
            o0.y = fmaxf(acc[mt][nt][1] + b1, 0.f);
            o1.x = fmaxf(acc[mt][nt][2] + b0, 0.f);
            o1.y = fmaxf(acc[mt][nt][3] + b1, 0.f);
            *(float2*)(g_hidden + (size_t)row * HID + n0 + colL) = o0;
            *(float2*)(g_hidden + (size_t)(row + 8) * HID + n0 + colL) = o1;
        }
}

// ---------------------------------------------------------------------------
// Heads: one warp per 2 agents; Ws/Wc staged in smem
// ---------------------------------------------------------------------------
#define RED_OFF 0
#define WS_OFF  33792                   // 8*32*33*4
#define WC_OFF  (WS_OFF + 32 * 512 * 4)
#define HEAD_SMEM (WC_OFF + 512 * 4)    // 101376 B

__global__ __launch_bounds__(256) void head_kernel(
    const float* __restrict__ Ws, const float* __restrict__ bs,
    const float* __restrict__ Wc, const float* __restrict__ bc,
    const int* __restrict__ skill, const int* __restrict__ action,
    float* __restrict__ out)
{
    extern __shared__ __align__(16) unsigned char hsm[];
    float* red  = (float*)(hsm + RED_OFF);   // [8][32][33]
    float* ws_s = (float*)(hsm + WS_OFF);    // [32][512]
    float* wc_s = (float*)(hsm + WC_OFF);    // [512]

    const int tid = threadIdx.x;
#pragma unroll
    for (int i = 0; i < 16; i++)
        ((float4*)ws_s)[i * 256 + tid] = ((const float4*)Ws)[i * 256 + tid];
    if (tid < 128) ((float4*)wc_s)[tid] = ((const float4*)Wc)[tid];
    __syncthreads();

    const int lane = tid & 31;
    const int w    = tid >> 5;
    const int a0   = (blockIdx.x * 8 + w) * 2;

    const float* h0 = g_hidden + (size_t)a0 * HID;

    float acc[2][33];
#pragma unroll
    for (int s = 0; s < 2; s++)
#pragma unroll
        for (int i = 0; i < 33; i++) acc[s][i] = 0.f;

#pragma unroll 4
    for (int j = 0; j < HID / 32; j++) {
        const int k = j * 32 + lane;
        const float hv0 = h0[k];
        const float hv1 = h0[HID + k];
#pragma unroll
        for (int t = 0; t < 32; t++) {
            const float wv = ws_s[t * HID + k];
            acc[0][t] += hv0 * wv;
            acc[1][t] += hv1 * wv;
        }
        const float wc = wc_s[k];
        acc[0][32] += hv0 * wc;
        acc[1][32] += hv1 * wc;
    }

    const float bsl = bs[lane];
    const float bcv = bc[0];
    float* redw = red + w * 32 * 33;

#pragma unroll
    for (int s = 0; s < 2; s++) {
        const int agent = a0 + s;

        float v = acc[s][32];
#pragma unroll
        for (int o = 16; o > 0; o >>= 1) v += __shfl_xor_sync(0xffffffffu, v, o);

#pragma unroll
        for (int t = 0; t < 32; t++) redw[lane * 33 + t] = acc[s][t];
        __syncwarp();
        float logit = 0.f;
#pragma unroll
        for (int q = 0; q < 32; q++) logit += redw[q * 33 + lane];
        __syncwarp();
        logit += bsl;

        float mx = logit;
#pragma unroll
        for (int o = 16; o > 0; o >>= 1) mx = fmaxf(mx, __shfl_xor_sync(0xffffffffu, mx, o));
        const float e = expf(logit - mx);
        float se = e;
#pragma unroll
        for (int o = 16; o > 0; o >>= 1) se += __shfl_xor_sync(0xffffffffu, se, o);
        const float lse = mx + logf(se);
        const float lsm = logit - lse;
        float ent = -(e / se) * lsm;
#pragma unroll
        for (int o = 16; o > 0; o >>= 1) ent += __shfl_xor_sync(0xffffffffu, ent, o);

        const int act = action[agent];
        const float slp = __shfl_sync(0xffffffffu, lsm, act & 31);

        if (lane == 0) {
            out[0 * N_AGENTS + agent] = (float)act;
            out[1 * N_AGENTS + agent] = (float)skill[agent];
            out[2 * N_AGENTS + agent] = -2.7725887222397811f;  // -ln(16)
            out[3 * N_AGENTS + agent] = slp;
            out[4 * N_AGENTS + agent] = ent;
            out[5 * N_AGENTS + agent] = v + bcv;
        }
    }
}

// ---------------------------------------------------------------------------
// launch
// ---------------------------------------------------------------------------
extern "C" void kernel_launch(void* const* d_in, const int* in_sizes, int n_in,
                              void* d_out, int out_size) {
    (void)in_sizes; (void)n_in; (void)out_size;
    const float* x     = (const float*)d_in[0];
    const float* W_enc = (const float*)d_in[1];
    const float* b_enc = (const float*)d_in[2];
    // d_in[3]=Wm, d_in[4]=bm : dead (selections never returned)
    const float* Ws    = (const float*)d_in[5];
    const float* bs    = (const float*)d_in[6];
    const float* Wc    = (const float*)d_in[7];
    const float* bc    = (const float*)d_in[8];
    const int*   skill = (const int*)d_in[9];
    const int*   act   = (const int*)d_in[10];
    float* out = (float*)d_out;

    unsigned char* dA;
    cudaGetSymbolAddress((void**)&dA, g_Astage);
    unsigned char* dB;
    cudaGetSymbolAddress((void**)&dB, g_Bstage);

    static int cfg_done = 0;
    if (!cfg_done) {
        cudaFuncSetAttribute(enc_gemm_mma, cudaFuncAttributeMaxDynamicSharedMemorySize,
                             SMEM_TOTAL);
        cudaFuncSetAttribute(head_kernel, cudaFuncAttributeMaxDynamicSharedMemorySize,
                             HEAD_SMEM);
        cfg_done = 1;
    }

    conv_kernel<<<512, 256>>>(W_enc, dB);                 // 512 rows
    conv_kernel<<<N_AGENTS, 256>>>(x, dA);                // 16384 rows

    enc_gemm_mma<<<NTILES * MTILES, 256, SMEM_TOTAL>>>(b_enc);

    head_kernel<<<N_AGENTS / 16, 256, HEAD_SMEM>>>(Ws, bs, Wc, bc, skill, act, out);
}